// round 1
// baseline (speedup 1.0000x reference)
#include <cuda_runtime.h>
#include <math.h>

#define Bv 128
#define Tv 64
#define Cv 66
#define Sv 512
#define Wwin 32
#define G3 1536
#define TENC 63
#define NSTEP 127

// ---------------- device scratch (static, allowed) ----------------
__device__ float g_h0[Bv * Sv];
__device__ float g_h1[Bv * Sv];
__device__ float g_hist[NSTEP * Bv * Sv];      // h1 history (33 MB)
__device__ float g_gi0[TENC * Bv * G3];        // precomputed encoder gi0 (49.5 MB)
__device__ float g_gi0d[Bv * G3];              // decoder gi0 (frame @ Wih0^T)
__device__ float g_gh0[Bv * G3];
__device__ float g_gh1[Bv * G3];
__device__ float g_gi1[Bv * G3];
__device__ float g_temp[Bv * Sv];
__device__ float g_frame[Bv * Cv];
__device__ unsigned int g_arrive;

// ---------------- grid barrier ----------------
__device__ __forceinline__ void gsync(unsigned int &tgt, int nb) {
    __syncthreads();
    tgt += (unsigned)nb;
    if (threadIdx.x == 0) {
        __threadfence();                 // release (flushes L1 on sm_103a)
        atomicAdd(&g_arrive, 1u);
        while (*(volatile unsigned int *)&g_arrive < tgt) { }
        __threadfence();                 // acquire / re-invalidate L1
    }
    __syncthreads();
}

// ---------------- 64x64 output tile GEMM: Out[m,n] = A[m,:K] . Wm[n,:K] + bias[n]
// A is [128, lda] row-major (cross-SM written -> __ldcg), Wm is [1536, K] row-major.
// Out is [128, 1536] row-major.
__device__ __forceinline__ void gemm_tile(
    const float *__restrict__ A, int lda,
    const float *__restrict__ Wm,
    const float *__restrict__ bias,
    float *__restrict__ Out,
    int K, int m0, int n0,
    float *shA, float *shW)
{
    const int tid = threadIdx.x;
    const int tx = tid & 15;   // col group
    const int ty = tid >> 4;   // row group
    float acc[4][4];
#pragma unroll
    for (int i = 0; i < 4; i++)
#pragma unroll
        for (int j = 0; j < 4; j++) acc[i][j] = 0.f;

    for (int kc = 0; kc < K; kc += 32) {
#pragma unroll
        for (int it = 0; it < 8; it++) {
            int i = tid + it * 256;
            int r = i >> 5, c = i & 31;
            int kk = kc + c;
            float av = 0.f, wv = 0.f;
            if (kk < K) {
                av = __ldcg(&A[(m0 + r) * lda + kk]);
                wv = __ldg(&Wm[(n0 + r) * K + kk]);
            }
            shA[c * 68 + r] = av;
            shW[c * 68 + r] = wv;
        }
        __syncthreads();
#pragma unroll
        for (int k = 0; k < 32; ++k) {
            const float4 avv = *reinterpret_cast<const float4 *>(shA + k * 68 + (ty << 2));
            const float4 bvv = *reinterpret_cast<const float4 *>(shW + k * 68 + (tx << 2));
            const float a0 = avv.x, a1 = avv.y, a2 = avv.z, a3 = avv.w;
            const float b0 = bvv.x, b1 = bvv.y, b2 = bvv.z, b3 = bvv.w;
            acc[0][0] += a0 * b0; acc[0][1] += a0 * b1; acc[0][2] += a0 * b2; acc[0][3] += a0 * b3;
            acc[1][0] += a1 * b0; acc[1][1] += a1 * b1; acc[1][2] += a1 * b2; acc[1][3] += a1 * b3;
            acc[2][0] += a2 * b0; acc[2][1] += a2 * b1; acc[2][2] += a2 * b2; acc[2][3] += a2 * b3;
            acc[3][0] += a3 * b0; acc[3][1] += a3 * b1; acc[3][2] += a3 * b2; acc[3][3] += a3 * b3;
        }
        __syncthreads();
    }
#pragma unroll
    for (int i = 0; i < 4; i++) {
        int rr = m0 + (ty << 2) + i;
        float *orow = Out + rr * G3 + n0 + (tx << 2);
#pragma unroll
        for (int j = 0; j < 4; j++)
            orow[j] = acc[i][j] + __ldg(&bias[n0 + (tx << 2) + j]);
    }
}

// ---------------- kernel 1: init state + precompute encoder gi0 ----------------
// GI0[t][b][n] = sum_c x[b,t,c] * Wih0[n,c] + bih0[n], t = 0..62
// rows r = t*128 + b (8064 rows), tiles 64x64 -> grid 126*24 = 3024 blocks.
__global__ void __launch_bounds__(256) pre_kernel(
    const float *__restrict__ x,
    const float *__restrict__ Wih0,
    const float *__restrict__ bih0)
{
    __shared__ __align__(16) float shA[32 * 68];
    __shared__ __align__(16) float shW[32 * 68];
    const int tid = threadIdx.x;

    if (blockIdx.x == 0) {
        for (int i = tid; i < Bv * Sv; i += 256) { g_h0[i] = 0.f; g_h1[i] = 0.f; }
        for (int i = tid; i < Bv * Cv; i += 256) {
            int b = i / Cv, c = i - b * Cv;
            g_frame[i] = x[b * Tv * Cv + (Tv - 1) * Cv + c];
        }
        if (tid == 0) g_arrive = 0u;
    }

    const int rt = blockIdx.x / 24;
    const int nt = blockIdx.x % 24;
    const int r0 = rt * 64, n0 = nt * 64;
    const int tx = tid & 15, ty = tid >> 4;

    float acc[4][4];
#pragma unroll
    for (int i = 0; i < 4; i++)
#pragma unroll
        for (int j = 0; j < 4; j++) acc[i][j] = 0.f;

    for (int kc = 0; kc < Cv; kc += 32) {
#pragma unroll
        for (int it = 0; it < 8; it++) {
            int i = tid + it * 256;
            int r = i >> 5, c = i & 31;
            int kk = kc + c;
            float av = 0.f, wv = 0.f;
            if (kk < Cv) {
                int rr = r0 + r;
                int t = rr >> 7, b = rr & 127;
                av = __ldg(&x[b * (Tv * Cv) + t * Cv + kk]);
                wv = __ldg(&Wih0[(n0 + r) * Cv + kk]);
            }
            shA[c * 68 + r] = av;
            shW[c * 68 + r] = wv;
        }
        __syncthreads();
#pragma unroll
        for (int k = 0; k < 32; ++k) {
            const float4 avv = *reinterpret_cast<const float4 *>(shA + k * 68 + (ty << 2));
            const float4 bvv = *reinterpret_cast<const float4 *>(shW + k * 68 + (tx << 2));
            const float a0 = avv.x, a1 = avv.y, a2 = avv.z, a3 = avv.w;
            const float b0 = bvv.x, b1 = bvv.y, b2 = bvv.z, b3 = bvv.w;
            acc[0][0] += a0 * b0; acc[0][1] += a0 * b1; acc[0][2] += a0 * b2; acc[0][3] += a0 * b3;
            acc[1][0] += a1 * b0; acc[1][1] += a1 * b1; acc[1][2] += a1 * b2; acc[1][3] += a1 * b3;
            acc[2][0] += a2 * b0; acc[2][1] += a2 * b1; acc[2][2] += a2 * b2; acc[2][3] += a2 * b3;
            acc[3][0] += a3 * b0; acc[3][1] += a3 * b1; acc[3][2] += a3 * b2; acc[3][3] += a3 * b3;
        }
        __syncthreads();
    }
#pragma unroll
    for (int i = 0; i < 4; i++) {
        int rr = r0 + (ty << 2) + i;
        int t = rr >> 7, b = rr & 127;
        float *orow = g_gi0 + t * (Bv * G3) + b * G3 + n0 + (tx << 2);
#pragma unroll
        for (int j = 0; j < 4; j++)
            orow[j] = acc[i][j] + __ldg(&bih0[n0 + (tx << 2) + j]);
    }
}

__device__ __forceinline__ float sigf(float v) { return 1.f / (1.f + expf(-v)); }

// ---------------- kernel 2: persistent sequential RNN ----------------
__global__ void __launch_bounds__(256, 1) rnn_kernel(
    const float *__restrict__ Wih0, const float *__restrict__ bih0,
    const float *__restrict__ Whh0, const float *__restrict__ bhh0,
    const float *__restrict__ Wih1, const float *__restrict__ bih1,
    const float *__restrict__ Whh1, const float *__restrict__ bhh1,
    const float *__restrict__ Wt, const float *__restrict__ bt,
    const float *__restrict__ Ws, const float *__restrict__ bs,
    float *__restrict__ out, int nb)
{
    __shared__ __align__(16) float shA[32 * 68];
    __shared__ __align__(16) float shW[32 * 68];
    const int bid = blockIdx.x;
    const int tid = threadIdx.x;
    const int nth = nb * 256;
    const int gtid = bid * 256 + tid;
    unsigned int tgt = 0;

    for (int step = 0; step < NSTEP; step++) {
        const bool dec = (step >= TENC);
        const int d = step - TENC;

        // ---- Phase A: gh0 (48 tiles) + gh1 (48 tiles) + [dec] gi0d (48 tiles)
        {
            int ntasks = dec ? 144 : 96;
            for (int task = bid; task < ntasks; task += nb) {
                int g = task / 48;
                int sub = task - g * 48;
                int m0 = (sub / 24) * 64;
                int n0 = (sub % 24) * 64;
                if (g == 0)
                    gemm_tile(g_h0, Sv, Whh0, bhh0, g_gh0, Sv, m0, n0, shA, shW);
                else if (g == 1)
                    gemm_tile(g_h1, Sv, Whh1, bhh1, g_gh1, Sv, m0, n0, shA, shW);
                else
                    gemm_tile(g_frame, Cv, Wih0, bih0, g_gi0d, Cv, m0, n0, shA, shW);
            }
        }
        gsync(tgt, nb);

        // ---- gate h0
        {
            const float *GI = dec ? g_gi0d : (g_gi0 + step * (Bv * G3));
            for (int idx = gtid; idx < Bv * Sv; idx += nth) {
                int b = idx >> 9, s = idx & 511;
                const float *gib = GI + b * G3;
                const float *ghb = g_gh0 + b * G3;
                float ir = __ldcg(gib + s),        hr = __ldcg(ghb + s);
                float iz = __ldcg(gib + 512 + s),  hz = __ldcg(ghb + 512 + s);
                float in_ = __ldcg(gib + 1024 + s), hn = __ldcg(ghb + 1024 + s);
                float r = sigf(ir + hr);
                float z = sigf(iz + hz);
                float n = tanhf(in_ + r * hn);
                g_h0[idx] = (1.f - z) * n + z * g_h0[idx];
            }
        }
        gsync(tgt, nb);

        // ---- Phase B: gi1 = h0_new @ Wih1^T + bih1 (48 tiles)
        for (int task = bid; task < 48; task += nb) {
            int m0 = (task / 24) * 64;
            int n0 = (task % 24) * 64;
            gemm_tile(g_h0, Sv, Wih1, bih1, g_gi1, Sv, m0, n0, shA, shW);
        }
        gsync(tgt, nb);

        // ---- gate h1 (+ history store, + decoder window reduction)
        {
            float bt0 = __ldg(&bt[0]);
            for (int idx = gtid; idx < Bv * Sv; idx += nth) {
                int b = idx >> 9, s = idx & 511;
                const float *gib = g_gi1 + b * G3;
                const float *ghb = g_gh1 + b * G3;
                float ir = __ldcg(gib + s),        hr = __ldcg(ghb + s);
                float iz = __ldcg(gib + 512 + s),  hz = __ldcg(ghb + 512 + s);
                float in_ = __ldcg(gib + 1024 + s), hn = __ldcg(ghb + 1024 + s);
                float r = sigf(ir + hr);
                float z = sigf(iz + hz);
                float n = tanhf(in_ + r * hn);
                float h1n = (1.f - z) * n + z * g_h1[idx];
                g_h1[idx] = h1n;
                g_hist[step * (Bv * Sv) + idx] = h1n;
                if (dec) {
                    float acc = bt0;
#pragma unroll
                    for (int w = 0; w < Wwin - 1; w++)
                        acc += __ldg(&Wt[w]) * g_hist[(32 + d + w) * (Bv * Sv) + idx];
                    acc += __ldg(&Wt[Wwin - 1]) * h1n;
                    g_temp[idx] = acc;
                }
            }
        }
        gsync(tgt, nb);

        // ---- decoder Phase D: out = temp @ Ws^T + bs; frame += out; emit
        if (dec) {
            if (bid < Bv) {
                const int b = bid;
                float *shT = shA;   // 512 floats
                float *shR = shW;   // 132 floats
                for (int s = tid; s < Sv; s += 256)
                    shT[s] = __ldcg(&g_temp[b * Sv + s]);
                __syncthreads();
                float p = 0.f;
                if (tid < 2 * Cv) {
                    int c = tid >> 1, h = tid & 1;
                    const float *wr = Ws + c * Sv + h * 256;
                    const float *tr = shT + h * 256;
                    float p0 = 0.f, p1 = 0.f, p2 = 0.f, p3 = 0.f;
#pragma unroll 4
                    for (int s = 0; s < 256; s += 4) {
                        p0 += tr[s + 0] * __ldg(&wr[s + 0]);
                        p1 += tr[s + 1] * __ldg(&wr[s + 1]);
                        p2 += tr[s + 2] * __ldg(&wr[s + 2]);
                        p3 += tr[s + 3] * __ldg(&wr[s + 3]);
                    }
                    p = (p0 + p1) + (p2 + p3);
                    shR[tid] = p;
                }
                __syncthreads();
                if (tid < Cv) {
                    float ov = shR[2 * tid] + shR[2 * tid + 1] + __ldg(&bs[tid]);
                    float nf = ov + g_frame[b * Cv + tid];
                    out[b * (Tv * Cv) + d * Cv + tid] = nf;
                    g_frame[b * Cv + tid] = nf;
                }
            }
            gsync(tgt, nb);
        }
    }
}

// ---------------- launch ----------------
extern "C" void kernel_launch(void *const *d_in, const int *in_sizes, int n_in,
                              void *d_out, int out_size)
{
    const float *x    = (const float *)d_in[0];
    const float *Wih0 = (const float *)d_in[1];
    const float *Whh0 = (const float *)d_in[2];
    const float *bih0 = (const float *)d_in[3];
    const float *bhh0 = (const float *)d_in[4];
    const float *Wih1 = (const float *)d_in[5];
    const float *Whh1 = (const float *)d_in[6];
    const float *bih1 = (const float *)d_in[7];
    const float *bhh1 = (const float *)d_in[8];
    const float *Wt   = (const float *)d_in[9];
    const float *bt   = (const float *)d_in[10];
    const float *Ws   = (const float *)d_in[11];
    const float *bs   = (const float *)d_in[12];
    float *out = (float *)d_out;

    int dev = 0;
    cudaGetDevice(&dev);
    int nb = 0;
    cudaDeviceGetAttribute(&nb, cudaDevAttrMultiProcessorCount, dev);
    if (nb <= 0) nb = 148;

    pre_kernel<<<126 * 24, 256>>>(x, Wih0, bih0);
    rnn_kernel<<<nb, 256>>>(Wih0, bih0, Whh0, bhh0, Wih1, bih1, Whh1, bhh1,
                            Wt, bt, Ws, bs, out, nb);
}

// round 2
// speedup vs baseline: 1.6965x; 1.6965x over previous
#include <cuda_runtime.h>
#include <math.h>

#define Bv 128
#define Tv 64
#define Cv 66
#define Sv 512
#define Wwin 32
#define G3 1536
#define TENC 63
#define NSTEP 127
#define KH 256

// ---------------- device scratch ----------------
__device__ float g_h0[Bv * Sv];
__device__ float g_h1[Bv * Sv];
__device__ float g_hist[NSTEP * Bv * Sv];
__device__ float g_gi0[TENC * Bv * G3];   // precomputed encoder x@Wih0^T (NO bias)
__device__ float g_gi0d[Bv * G3];         // decoder frame@Wih0^T (NO bias)
__device__ float g_gh0a[Bv * G3];
__device__ float g_gh0b[Bv * G3];
__device__ float g_gh1a[Bv * G3];
__device__ float g_gh1b[Bv * G3];
__device__ float g_gi1a[Bv * G3];
__device__ float g_gi1b[Bv * G3];
__device__ float g_frame[Bv * Cv];
__device__ unsigned int g_arrive;

// ---------------- grid barrier ----------------
__device__ __forceinline__ void gsync(unsigned int &tgt, int nb) {
    __syncthreads();
    tgt += (unsigned)nb;
    if (threadIdx.x == 0) {
        __threadfence();
        atomicAdd(&g_arrive, 1u);
        while (*(volatile unsigned int *)&g_arrive < tgt) { }
        __threadfence();
    }
    __syncthreads();
}

__device__ __forceinline__ float sigf(float v) { return 1.f / (1.f + expf(-v)); }

__device__ __forceinline__ float4 ldcg4(const float *p) {
    return __ldcg(reinterpret_cast<const float4 *>(p));
}
__device__ __forceinline__ float4 ldg4(const float *p) {
    return __ldg(reinterpret_cast<const float4 *>(p));
}

// ---------------- 64x64 tile GEMM, arbitrary K window, raw partial output ----
// Out[m0+i, n0+j] = sum_{k in [k0, k0+kLen)} A[m,k] * Wm[n,k]
// Register-prefetch double buffering hides global-load latency.
__device__ __forceinline__ void gemm_tile(
    const float *__restrict__ A, int lda,
    const float *__restrict__ Wm, int ldw,
    float *__restrict__ Out,
    int m0, int n0, int k0, int kLen,
    float *shA, float *shW)
{
    const int tid = threadIdx.x;
    const int tx = tid & 15;
    const int ty = tid >> 4;
    const int lr = tid >> 5;   // 0..7
    const int lc = tid & 31;   // k lane within chunk
    float acc[4][4];
#pragma unroll
    for (int i = 0; i < 4; i++)
#pragma unroll
        for (int j = 0; j < 4; j++) acc[i][j] = 0.f;

    const int nCh = (kLen + 31) >> 5;
    float pa[8], pw[8];
    {
        const bool ok = lc < kLen;
#pragma unroll
        for (int it = 0; it < 8; it++) {
            int r = lr + it * 8;
            pa[it] = ok ? __ldcg(&A[(m0 + r) * lda + k0 + lc]) : 0.f;
            pw[it] = ok ? __ldg(&Wm[(n0 + r) * ldw + k0 + lc]) : 0.f;
        }
    }

    for (int ch = 0; ch < nCh; ++ch) {
        __syncthreads();
#pragma unroll
        for (int it = 0; it < 8; it++) {
            int r = lr + it * 8;
            shA[lc * 68 + r] = pa[it];
            shW[lc * 68 + r] = pw[it];
        }
        if (ch + 1 < nCh) {
            int kk = ((ch + 1) << 5) + lc;
            const bool ok = kk < kLen;
#pragma unroll
            for (int it = 0; it < 8; it++) {
                int r = lr + it * 8;
                pa[it] = ok ? __ldcg(&A[(m0 + r) * lda + k0 + kk]) : 0.f;
                pw[it] = ok ? __ldg(&Wm[(n0 + r) * ldw + k0 + kk]) : 0.f;
            }
        }
        __syncthreads();
#pragma unroll
        for (int k = 0; k < 32; ++k) {
            const float4 avv = *reinterpret_cast<const float4 *>(shA + k * 68 + (ty << 2));
            const float4 bvv = *reinterpret_cast<const float4 *>(shW + k * 68 + (tx << 2));
            const float a0 = avv.x, a1 = avv.y, a2 = avv.z, a3 = avv.w;
            const float b0 = bvv.x, b1 = bvv.y, b2 = bvv.z, b3 = bvv.w;
            acc[0][0] += a0 * b0; acc[0][1] += a0 * b1; acc[0][2] += a0 * b2; acc[0][3] += a0 * b3;
            acc[1][0] += a1 * b0; acc[1][1] += a1 * b1; acc[1][2] += a1 * b2; acc[1][3] += a1 * b3;
            acc[2][0] += a2 * b0; acc[2][1] += a2 * b1; acc[2][2] += a2 * b2; acc[2][3] += a2 * b3;
            acc[3][0] += a3 * b0; acc[3][1] += a3 * b1; acc[3][2] += a3 * b2; acc[3][3] += a3 * b3;
        }
    }
#pragma unroll
    for (int i = 0; i < 4; i++) {
        float4 v = make_float4(acc[i][0], acc[i][1], acc[i][2], acc[i][3]);
        *reinterpret_cast<float4 *>(&Out[(m0 + (ty << 2) + i) * G3 + n0 + (tx << 2)]) = v;
    }
}

// ---------------- kernel 1: init + precompute encoder gi0 (no bias) --------
__global__ void __launch_bounds__(256) pre_kernel(
    const float *__restrict__ x,
    const float *__restrict__ Wih0)
{
    __shared__ __align__(16) float shA[32 * 68];
    __shared__ __align__(16) float shW[32 * 68];
    const int tid = threadIdx.x;

    if (blockIdx.x == 0) {
        for (int i = tid; i < Bv * Sv; i += 256) { g_h0[i] = 0.f; g_h1[i] = 0.f; }
        for (int i = tid; i < Bv * Cv; i += 256) {
            int b = i / Cv, c = i - b * Cv;
            g_frame[i] = x[b * Tv * Cv + (Tv - 1) * Cv + c];
        }
        if (tid == 0) g_arrive = 0u;
    }

    const int rt = blockIdx.x / 24;
    const int nt = blockIdx.x % 24;
    const int r0 = rt * 64, n0 = nt * 64;
    const int tx = tid & 15, ty = tid >> 4;
    const int lr = tid >> 5, lc = tid & 31;

    float acc[4][4];
#pragma unroll
    for (int i = 0; i < 4; i++)
#pragma unroll
        for (int j = 0; j < 4; j++) acc[i][j] = 0.f;

    for (int kc = 0; kc < Cv; kc += 32) {
        __syncthreads();
#pragma unroll
        for (int it = 0; it < 8; it++) {
            int r = lr + it * 8;
            int kk = kc + lc;
            float av = 0.f, wv = 0.f;
            if (kk < Cv) {
                int rr = r0 + r;
                int t = rr >> 7, b = rr & 127;
                av = __ldg(&x[b * (Tv * Cv) + t * Cv + kk]);
                wv = __ldg(&Wih0[(n0 + r) * Cv + kk]);
            }
            shA[lc * 68 + r] = av;
            shW[lc * 68 + r] = wv;
        }
        __syncthreads();
#pragma unroll
        for (int k = 0; k < 32; ++k) {
            const float4 avv = *reinterpret_cast<const float4 *>(shA + k * 68 + (ty << 2));
            const float4 bvv = *reinterpret_cast<const float4 *>(shW + k * 68 + (tx << 2));
            const float a0 = avv.x, a1 = avv.y, a2 = avv.z, a3 = avv.w;
            const float b0 = bvv.x, b1 = bvv.y, b2 = bvv.z, b3 = bvv.w;
            acc[0][0] += a0 * b0; acc[0][1] += a0 * b1; acc[0][2] += a0 * b2; acc[0][3] += a0 * b3;
            acc[1][0] += a1 * b0; acc[1][1] += a1 * b1; acc[1][2] += a1 * b2; acc[1][3] += a1 * b3;
            acc[2][0] += a2 * b0; acc[2][1] += a2 * b1; acc[2][2] += a2 * b2; acc[2][3] += a2 * b3;
            acc[3][0] += a3 * b0; acc[3][1] += a3 * b1; acc[3][2] += a3 * b2; acc[3][3] += a3 * b3;
        }
    }
#pragma unroll
    for (int i = 0; i < 4; i++) {
        int rr = r0 + (ty << 2) + i;
        int t = rr >> 7, b = rr & 127;
        float4 v = make_float4(acc[i][0], acc[i][1], acc[i][2], acc[i][3]);
        *reinterpret_cast<float4 *>(&g_gi0[t * (Bv * G3) + b * G3 + n0 + (tx << 2)]) = v;
    }
}

// ---------------- kernel 2: persistent sequential RNN ----------------
__global__ void __launch_bounds__(256, 1) rnn_kernel(
    const float *__restrict__ Wih0, const float *__restrict__ bih0,
    const float *__restrict__ Whh0, const float *__restrict__ bhh0,
    const float *__restrict__ Wih1, const float *__restrict__ bih1,
    const float *__restrict__ Whh1, const float *__restrict__ bhh1,
    const float *__restrict__ Wt, const float *__restrict__ bt,
    const float *__restrict__ Ws, const float *__restrict__ bs,
    float *__restrict__ out, int nb)
{
    __shared__ __align__(16) float shA[32 * 68];
    __shared__ __align__(16) float shW[32 * 68];
    __shared__ float shWt[32];
    const int bid = blockIdx.x;
    const int tid = threadIdx.x;
    const int nth = nb * 256;
    const int gtid = bid * 256 + tid;
    unsigned int tgt = 0;

    for (int step = 0; step < NSTEP; step++) {
        const bool dec = (step >= TENC);
        const int d = step - TENC;

        // ======== Phase A: gh0 (split-K2, 96) + gh1 half0 (48) + [dec] gi0d (48)
        {
            const int ntA = dec ? 192 : 144;
            for (int task = bid; task < ntA; task += nb) {
                if (task < 96) {
                    int half = task / 48, sub = task - half * 48;
                    int m0 = (sub / 24) * 64, n0 = (sub % 24) * 64;
                    gemm_tile(g_h0, Sv, Whh0, Sv, half ? g_gh0b : g_gh0a,
                              m0, n0, half * KH, KH, shA, shW);
                } else if (task < 144) {
                    int sub = task - 96;
                    int m0 = (sub / 24) * 64, n0 = (sub % 24) * 64;
                    gemm_tile(g_h1, Sv, Whh1, Sv, g_gh1a, m0, n0, 0, KH, shA, shW);
                } else {
                    int sub = task - 144;
                    int m0 = (sub / 24) * 64, n0 = (sub % 24) * 64;
                    gemm_tile(g_frame, Cv, Wih0, Cv, g_gi0d, m0, n0, 0, Cv, shA, shW);
                }
            }
        }
        gsync(tgt, nb);

        // ======== gate0: h0 update (float4 over 16384 groups)
        {
            const float *GI = dec ? g_gi0d : (g_gi0 + step * (Bv * G3));
            for (int g = gtid; g < (Bv * Sv) / 4; g += nth) {
                int v = g << 2;
                int b = v >> 9, s = v & 511;
                const float *gib = GI + b * G3;
                const float *gha = g_gh0a + b * G3;
                const float *ghb = g_gh0b + b * G3;

                float4 ir = ldcg4(gib + s);
                float4 iz = ldcg4(gib + 512 + s);
                float4 in_ = ldcg4(gib + 1024 + s);
                float4 bi_r = ldg4(bih0 + s), bi_z = ldg4(bih0 + 512 + s), bi_n = ldg4(bih0 + 1024 + s);
                float4 hra = ldcg4(gha + s), hrb = ldcg4(ghb + s);
                float4 hza = ldcg4(gha + 512 + s), hzb = ldcg4(ghb + 512 + s);
                float4 hna = ldcg4(gha + 1024 + s), hnb = ldcg4(ghb + 1024 + s);
                float4 bh_r = ldg4(bhh0 + s), bh_z = ldg4(bhh0 + 512 + s), bh_n = ldg4(bhh0 + 1024 + s);
                float4 hold = *reinterpret_cast<const float4 *>(g_h0 + v);

                float rr[4], zz[4], nn[4], ho[4], res[4];
                float irr[4] = {ir.x + bi_r.x, ir.y + bi_r.y, ir.z + bi_r.z, ir.w + bi_r.w};
                float izz[4] = {iz.x + bi_z.x, iz.y + bi_z.y, iz.z + bi_z.z, iz.w + bi_z.w};
                float inn[4] = {in_.x + bi_n.x, in_.y + bi_n.y, in_.z + bi_n.z, in_.w + bi_n.w};
                float hrr[4] = {hra.x + hrb.x + bh_r.x, hra.y + hrb.y + bh_r.y,
                                hra.z + hrb.z + bh_r.z, hra.w + hrb.w + bh_r.w};
                float hzz[4] = {hza.x + hzb.x + bh_z.x, hza.y + hzb.y + bh_z.y,
                                hza.z + hzb.z + bh_z.z, hza.w + hzb.w + bh_z.w};
                float hnn[4] = {hna.x + hnb.x + bh_n.x, hna.y + hnb.y + bh_n.y,
                                hna.z + hnb.z + bh_n.z, hna.w + hnb.w + bh_n.w};
                ho[0] = hold.x; ho[1] = hold.y; ho[2] = hold.z; ho[3] = hold.w;
#pragma unroll
                for (int q = 0; q < 4; q++) {
                    rr[q] = sigf(irr[q] + hrr[q]);
                    zz[q] = sigf(izz[q] + hzz[q]);
                    nn[q] = tanhf(inn[q] + rr[q] * hnn[q]);
                    res[q] = (1.f - zz[q]) * nn[q] + zz[q] * ho[q];
                }
                *reinterpret_cast<float4 *>(g_h0 + v) =
                    make_float4(res[0], res[1], res[2], res[3]);
            }
        }
        gsync(tgt, nb);

        // ======== Phase B: gi1 (split-K2, 96) + gh1 half1 (48)
        {
            for (int task = bid; task < 144; task += nb) {
                if (task < 96) {
                    int half = task / 48, sub = task - half * 48;
                    int m0 = (sub / 24) * 64, n0 = (sub % 24) * 64;
                    gemm_tile(g_h0, Sv, Wih1, Sv, half ? g_gi1b : g_gi1a,
                              m0, n0, half * KH, KH, shA, shW);
                } else {
                    int sub = task - 96;
                    int m0 = (sub / 24) * 64, n0 = (sub % 24) * 64;
                    gemm_tile(g_h1, Sv, Whh1, Sv, g_gh1b, m0, n0, KH, KH, shA, shW);
                }
            }
        }
        gsync(tgt, nb);

        // ======== gate1 (+ hist, window) + decoder projection, block b = row b
        if (bid < Bv) {
            const int b = bid;
            float *shT = shA;            // 512 floats (temp)
            float *shR = shW;            // partial dot results
            if (dec && tid < 32) shWt[tid] = __ldg(&Wt[tid]);
            __syncthreads();
            const float bt0 = __ldg(&bt[0]);

            for (int s = tid; s < Sv; s += 256) {
                const float *gia = g_gi1a + b * G3;
                const float *gib = g_gi1b + b * G3;
                const float *gha = g_gh1a + b * G3;
                const float *ghb = g_gh1b + b * G3;
                float ir = __ldcg(gia + s) + __ldcg(gib + s) + __ldg(&bih1[s]);
                float iz = __ldcg(gia + 512 + s) + __ldcg(gib + 512 + s) + __ldg(&bih1[512 + s]);
                float in_ = __ldcg(gia + 1024 + s) + __ldcg(gib + 1024 + s) + __ldg(&bih1[1024 + s]);
                float hr = __ldcg(gha + s) + __ldcg(ghb + s) + __ldg(&bhh0[0] + 0) * 0.f + __ldg(&bhh1[s]);
                float hz = __ldcg(gha + 512 + s) + __ldcg(ghb + 512 + s) + __ldg(&bhh1[512 + s]);
                float hn = __ldcg(gha + 1024 + s) + __ldcg(ghb + 1024 + s) + __ldg(&bhh1[1024 + s]);
                float r = sigf(ir + hr);
                float z = sigf(iz + hz);
                float n = tanhf(in_ + r * hn);
                float h1n = (1.f - z) * n + z * g_h1[b * Sv + s];
                g_h1[b * Sv + s] = h1n;
                g_hist[step * (Bv * Sv) + b * Sv + s] = h1n;
                if (dec) {
                    float acc = bt0;
                    const float *hp = g_hist + b * Sv + s;
#pragma unroll
                    for (int w = 0; w < Wwin - 1; w++)
                        acc += shWt[w] * hp[(32 + d + w) * (Bv * Sv)];
                    acc += shWt[Wwin - 1] * h1n;
                    shT[s] = acc;
                }
            }
            if (dec) {
                __syncthreads();
                if (tid < 2 * Cv) {
                    int c = tid >> 1, h = tid & 1;
                    const float *wr = Ws + c * Sv + h * 256;
                    const float *tr = shT + h * 256;
                    float p0 = 0.f, p1 = 0.f, p2 = 0.f, p3 = 0.f;
#pragma unroll 4
                    for (int s = 0; s < 256; s += 4) {
                        p0 += tr[s + 0] * __ldg(&wr[s + 0]);
                        p1 += tr[s + 1] * __ldg(&wr[s + 1]);
                        p2 += tr[s + 2] * __ldg(&wr[s + 2]);
                        p3 += tr[s + 3] * __ldg(&wr[s + 3]);
                    }
                    shR[tid] = (p0 + p1) + (p2 + p3);
                }
                __syncthreads();
                if (tid < Cv) {
                    float ov = shR[2 * tid] + shR[2 * tid + 1] + __ldg(&bs[tid]);
                    float nf = ov + g_frame[b * Cv + tid];
                    out[b * (Tv * Cv) + d * Cv + tid] = nf;
                    g_frame[b * Cv + tid] = nf;
                }
            }
        }
        gsync(tgt, nb);
    }
}

// ---------------- launch ----------------
extern "C" void kernel_launch(void *const *d_in, const int *in_sizes, int n_in,
                              void *d_out, int out_size)
{
    const float *x    = (const float *)d_in[0];
    const float *Wih0 = (const float *)d_in[1];
    const float *Whh0 = (const float *)d_in[2];
    const float *bih0 = (const float *)d_in[3];
    const float *bhh0 = (const float *)d_in[4];
    const float *Wih1 = (const float *)d_in[5];
    const float *Whh1 = (const float *)d_in[6];
    const float *bih1 = (const float *)d_in[7];
    const float *bhh1 = (const float *)d_in[8];
    const float *Wt   = (const float *)d_in[9];
    const float *bt   = (const float *)d_in[10];
    const float *Ws   = (const float *)d_in[11];
    const float *bs   = (const float *)d_in[12];
    float *out = (float *)d_out;

    int dev = 0;
    cudaGetDevice(&dev);
    int nb = 0;
    cudaDeviceGetAttribute(&nb, cudaDevAttrMultiProcessorCount, dev);
    if (nb <= 0) nb = 148;

    pre_kernel<<<126 * 24, 256>>>(x, Wih0);
    rnn_kernel<<<nb, 256>>>(Wih0, bih0, Whh0, bhh0, Wih1, bih1, Whh1, bhh1,
                            Wt, bt, Ws, bs, out, nb);
}